// round 6
// baseline (speedup 1.0000x reference)
#include <cuda_runtime.h>

namespace {
constexpr int N   = 512;
constexpr int D   = 64;
constexpr int C   = 32;
constexpr int HID = 128;
constexpr int NH  = 8;
constexpr int HD  = 16;
constexpr float SCALE = 0.25f;   // HEAD_DIM^-0.5
constexpr int THREADS = 256;
constexpr int NBT = 96;          // B*T

constexpr int WSTRIDE = 68;      // weight row stride (floats), 16B-aligned

constexpr int SW_OFF = 0;
constexpr int SW_SZ  = 3 * HD * WSTRIDE;    // 3264
constexpr int SQ_OFF = SW_OFF + SW_SZ;      // 3264  (13056B, 16B aligned)
constexpr int SQ_SZ  = N * HD;              // 8192
constexpr int SK_OFF = SQ_OFF + SQ_SZ;      // 11456
constexpr int SK_SZ  = N * HD;              // 8192 (16-float rows, XOR-swizzled)
constexpr int SV_OFF = SK_OFF + SK_SZ;      // 19648
constexpr int SV_SZ  = N * HD;              // 8192
constexpr int SMEM_FLOATS = SV_OFF + SV_SZ; // 27840 floats = 111360 B

constexpr int CLS_OFF    = SK_OFF;          // overlay cls_map onto dead K/V
constexpr int CLS_STRIDE = 512;             // 32*512 = 16384 = SK_SZ+SV_SZ exactly
}

// ---- packed fp32x2 helpers (Blackwell FFMA2; ptxas never emits from C++) ----
__device__ __forceinline__ unsigned long long f2_pack(float lo, float hi) {
    unsigned long long r;
    asm("mov.b64 %0, {%1, %2};" : "=l"(r) : "f"(lo), "f"(hi));
    return r;
}
__device__ __forceinline__ void f2_unpack(unsigned long long v, float& lo, float& hi) {
    asm("mov.b64 {%0, %1}, %2;" : "=f"(lo), "=f"(hi) : "l"(v));
}
__device__ __forceinline__ unsigned long long f2_mul(unsigned long long a, unsigned long long b) {
    unsigned long long d;
    asm("mul.rn.f32x2 %0, %1, %2;" : "=l"(d) : "l"(a), "l"(b));
    return d;
}
__device__ __forceinline__ unsigned long long f2_fma(unsigned long long a, unsigned long long b,
                                                     unsigned long long c) {
    unsigned long long d;
    asm("fma.rn.f32x2 %0, %1, %2, %3;" : "=l"(d) : "l"(a), "l"(b), "l"(c));
    return d;
}

__global__ __launch_bounds__(THREADS, 1)
void spatial_attn_kernel(const float* __restrict__ x,
                         const float* __restrict__ cls,
                         const float* __restrict__ Wq,
                         const float* __restrict__ Wk,
                         const float* __restrict__ Wv,
                         float* __restrict__ out) {
    extern __shared__ float smem[];

    const int blk = blockIdx.x;
    const int h   = blk & (NH - 1);
    const int bt  = blk >> 3;
    const float* xg   = x   + (size_t)bt * N * D;
    const float* clsg = cls + (size_t)bt * C * N;

    const int tid  = threadIdx.x;
    const int lane = tid & 31;
    const int wid  = tid >> 5;      // 0..7

    // ---- stage this head's weights into smem ----
    for (int idx = tid; idx < 3 * HD * D; idx += THREADS) {
        const int kind = idx >> 10;
        const int rem  = idx & 1023;
        const int e    = rem >> 6;
        const int d    = rem & 63;
        const float* Wsrc = (kind == 0) ? Wq : (kind == 1) ? Wk : Wv;
        smem[SW_OFF + kind * HD * WSTRIDE + e * WSTRIDE + d] = Wsrc[(h * HD + e) * D + d];
    }
    __syncthreads();

    // ---- projection: warp owns rows [wid*64, wid*64+64); x via broadcast LDG ----
    const int e    = lane & 15;
    const int half = lane >> 4;
    const float* sWq = smem + SW_OFF + 0 * HD * WSTRIDE + e * WSTRIDE;
    const float* sWk = smem + SW_OFF + 1 * HD * WSTRIDE + e * WSTRIDE;
    const float* sWv = smem + SW_OFF + 2 * HD * WSTRIDE + e * WSTRIDE;

    #pragma unroll
    for (int iter = 0; iter < 2; iter++) {
        const int rbase = wid * 64 + iter * 32 + half;   // rows rbase + 2r
        unsigned long long aq2[16], ak2[16], av2[16];
        #pragma unroll
        for (int r = 0; r < 16; r++) { aq2[r] = 0ULL; ak2[r] = 0ULL; av2[r] = 0ULL; }

        #pragma unroll 4
        for (int d4 = 0; d4 < 16; d4++) {
            const ulonglong2 wq2 = *reinterpret_cast<const ulonglong2*>(sWq + d4 * 4);
            const ulonglong2 wk2 = *reinterpret_cast<const ulonglong2*>(sWk + d4 * 4);
            const ulonglong2 wv2 = *reinterpret_cast<const ulonglong2*>(sWv + d4 * 4);
            #pragma unroll
            for (int r = 0; r < 16; r++) {
                const ulonglong2 x2 = *reinterpret_cast<const ulonglong2*>(
                    xg + (rbase + 2 * r) * D + d4 * 4);
                aq2[r] = f2_fma(x2.x, wq2.x, aq2[r]);
                aq2[r] = f2_fma(x2.y, wq2.y, aq2[r]);
                ak2[r] = f2_fma(x2.x, wk2.x, ak2[r]);
                ak2[r] = f2_fma(x2.y, wk2.y, ak2[r]);
                av2[r] = f2_fma(x2.x, wv2.x, av2[r]);
                av2[r] = f2_fma(x2.y, wv2.y, av2[r]);
            }
        }
        #pragma unroll
        for (int r = 0; r < 16; r++) {
            const int gr  = rbase + 2 * r;
            const int swz = (gr >> 1) & 3;                       // store-side XOR swizzle
            const int pos = (((e >> 2) ^ swz) << 2) + (e & 3);
            float lo, hi;
            f2_unpack(aq2[r], lo, hi);
            smem[SQ_OFF + gr * HD + e]   = (lo + hi) * SCALE;    // Q unswizzled, SCALE folded
            f2_unpack(ak2[r], lo, hi);
            smem[SK_OFF + gr * HD + pos] = lo + hi;
            f2_unpack(av2[r], lo, hi);
            smem[SV_OFF + gr * HD + pos] = lo + hi;
        }
    }
    __syncthreads();

    // ---- attention: warp handles its 64 rows, 8 at a time ----
    const int swz = (lane >> 1) & 3;   // load-side XOR swizzle (row m: (m>>1)&3 == (lane>>1)&3)

    for (int g = 0; g < 8; g++) {
        const int n0 = wid * 64 + g * 8;

        // QK^T in two 8-dim passes
        float s[8][16];
        #pragma unroll
        for (int pass = 0; pass < 2; pass++) {
            ulonglong2 qa[8], qb[8];
            #pragma unroll
            for (int r = 0; r < 8; r++) {
                const float* qp = smem + SQ_OFF + (n0 + r) * HD + pass * 8;
                qa[r] = *reinterpret_cast<const ulonglong2*>(qp);
                qb[r] = *reinterpret_cast<const ulonglong2*>(qp + 4);
            }
            const int c0 = ((2 * pass)     ^ swz) << 2;
            const int c1 = ((2 * pass + 1) ^ swz) << 2;

            #pragma unroll 4
            for (int i = 0; i < 16; i++) {
                const float* kr = smem + SK_OFF + (i * 32 + lane) * HD;
                const ulonglong2 k01 = *reinterpret_cast<const ulonglong2*>(kr + c0);
                const ulonglong2 k23 = *reinterpret_cast<const ulonglong2*>(kr + c1);
                #pragma unroll
                for (int r = 0; r < 8; r++) {
                    unsigned long long t = f2_mul(qa[r].x, k01.x);
                    t = f2_fma(qa[r].y, k01.y, t);
                    t = f2_fma(qb[r].x, k23.x, t);
                    t = f2_fma(qb[r].y, k23.y, t);
                    float lo, hi;
                    f2_unpack(t, lo, hi);
                    if (pass == 0) s[r][i] = lo + hi;
                    else           s[r][i] = s[r][i] + (lo + hi);
                }
            }
        }

        // softmax (no max subtraction: |s| <~ 13, fp32-safe); s -> p in place
        float inv[8];
        #pragma unroll
        for (int r = 0; r < 8; r++) {
            float ss = 0.f;
            #pragma unroll
            for (int i = 0; i < 16; i++) {
                const float p = __expf(s[r][i]);
                s[r][i] = p;
                ss += p;
            }
            #pragma unroll
            for (int off = 16; off > 0; off >>= 1)
                ss += __shfl_xor_sync(0xffffffffu, ss, off);
            inv[r] = __frcp_rn(ss);
        }

        // P @ V in two 8-dim passes, packed accumulators
        #pragma unroll
        for (int pass = 0; pass < 2; pass++) {
            const int c0 = ((2 * pass)     ^ swz) << 2;
            const int c1 = ((2 * pass + 1) ^ swz) << 2;

            unsigned long long acc2[8][4];
            #pragma unroll
            for (int r = 0; r < 8; r++)
                #pragma unroll
                for (int j = 0; j < 4; j++) acc2[r][j] = 0ULL;

            #pragma unroll 4
            for (int i = 0; i < 16; i++) {
                const float* vr = smem + SV_OFF + (i * 32 + lane) * HD;
                const ulonglong2 v01 = *reinterpret_cast<const ulonglong2*>(vr + c0);
                const ulonglong2 v23 = *reinterpret_cast<const ulonglong2*>(vr + c1);
                #pragma unroll
                for (int r = 0; r < 8; r++) {
                    const unsigned long long p2 = f2_pack(s[r][i], s[r][i]);
                    acc2[r][0] = f2_fma(p2, v01.x, acc2[r][0]);
                    acc2[r][1] = f2_fma(p2, v01.y, acc2[r][1]);
                    acc2[r][2] = f2_fma(p2, v23.x, acc2[r][2]);
                    acc2[r][3] = f2_fma(p2, v23.y, acc2[r][3]);
                }
            }

            // split-fold reduce: 8 dims over 32 lanes in 9 shfl per row
            const bool b4 = (lane & 16) != 0;
            const bool b3 = (lane & 8)  != 0;
            const bool b2 = (lane & 4)  != 0;
            #pragma unroll
            for (int r = 0; r < 8; r++) {
                float a[8];
                #pragma unroll
                for (int j = 0; j < 4; j++)
                    f2_unpack(acc2[r][j], a[2 * j], a[2 * j + 1]);
                #pragma unroll
                for (int j = 0; j < 4; j++) {
                    const float keepv = b4 ? a[4 + j] : a[j];
                    const float sendv = b4 ? a[j] : a[4 + j];
                    a[j] = keepv + __shfl_xor_sync(0xffffffffu, sendv, 16);
                }
                #pragma unroll
                for (int j = 0; j < 2; j++) {
                    const float keepv = b3 ? a[2 + j] : a[j];
                    const float sendv = b3 ? a[j] : a[2 + j];
                    a[j] = keepv + __shfl_xor_sync(0xffffffffu, sendv, 8);
                }
                {
                    const float keepv = b2 ? a[1] : a[0];
                    const float sendv = b2 ? a[0] : a[1];
                    a[0] = keepv + __shfl_xor_sync(0xffffffffu, sendv, 4);
                }
                a[0] += __shfl_xor_sync(0xffffffffu, a[0], 2);
                a[0] += __shfl_xor_sync(0xffffffffu, a[0], 1);
                if ((lane & 3) == 0) {
                    const int dmap = ((lane >> 4) & 1) * 4 + ((lane >> 3) & 1) * 2
                                   + ((lane >> 2) & 1);
                    smem[SQ_OFF + (n0 + r) * HD + pass * 8 + dmap] = a[0] * inv[r];
                }
            }
        }
    }
    __syncthreads();

    // ---- stage cls_map into dead K/V smem ----
    {
        const float4* src = reinterpret_cast<const float4*>(clsg);
        #pragma unroll
        for (int i = tid; i < C * N / 4; i += THREADS) {
            const int c  = i >> 7;
            const int n4 = i & 127;
            *reinterpret_cast<float4*>(smem + CLS_OFF + c * CLS_STRIDE + n4 * 4) = src[i];
        }
    }
    __syncthreads();

    // ---- cls pooling: thread (c = tid>>3, dims 2*(tid&7), +1) ----
    {
        const int c  = tid >> 3;
        const int d0 = (tid & 7) * 2;
        const float* pc  = smem + CLS_OFF + c * CLS_STRIDE;
        const float* psx = smem + SQ_OFF + d0;
        float a0 = 0.f, a1 = 0.f, a2 = 0.f, a3 = 0.f;
        #pragma unroll 4
        for (int n = 0; n < N; n += 4) {
            const float4 cl = *reinterpret_cast<const float4*>(pc + n);
            const float2 s0 = *reinterpret_cast<const float2*>(psx + (n + 0) * HD);
            const float2 s1 = *reinterpret_cast<const float2*>(psx + (n + 1) * HD);
            const float2 s2 = *reinterpret_cast<const float2*>(psx + (n + 2) * HD);
            const float2 s3 = *reinterpret_cast<const float2*>(psx + (n + 3) * HD);
            a0 = fmaf(cl.x, s0.x, a0);  a1 = fmaf(cl.x, s0.y, a1);
            a2 = fmaf(cl.y, s1.x, a2);  a3 = fmaf(cl.y, s1.y, a3);
            a0 = fmaf(cl.z, s2.x, a0);  a1 = fmaf(cl.z, s2.y, a1);
            a2 = fmaf(cl.w, s3.x, a2);  a3 = fmaf(cl.w, s3.y, a3);
        }
        float2 res;
        res.x = a0 + a2;
        res.y = a1 + a3;
        *reinterpret_cast<float2*>(out + ((size_t)bt * C + c) * HID + h * HD + d0) = res;
    }
}

extern "C" void kernel_launch(void* const* d_in, const int* in_sizes, int n_in,
                              void* d_out, int out_size) {
    const float* x   = (const float*)d_in[0];
    const float* cls = (const float*)d_in[1];
    const float* Wq  = (const float*)d_in[2];
    const float* Wk  = (const float*)d_in[3];
    const float* Wv  = (const float*)d_in[4];
    float* out = (float*)d_out;

    const size_t smem_bytes = (size_t)SMEM_FLOATS * sizeof(float);  // ~109 KB
    cudaFuncSetAttribute(spatial_attn_kernel,
                         cudaFuncAttributeMaxDynamicSharedMemorySize,
                         (int)smem_bytes);
    spatial_attn_kernel<<<NBT * NH, THREADS, smem_bytes>>>(x, cls, Wq, Wk, Wv, out);
}

// round 7
// speedup vs baseline: 1.3365x; 1.3365x over previous
#include <cuda_runtime.h>

namespace {
constexpr int N   = 512;
constexpr int D   = 64;
constexpr int C   = 32;
constexpr int HID = 128;
constexpr int NH  = 8;
constexpr int HD  = 16;
// fold 0.25 (head_dim^-0.5) and log2(e) into Q so softmax uses raw EX2
constexpr float SCALE_EX2 = 0.25f * 1.4426950408889634f;
constexpr int THREADS = 256;
constexpr int NBT = 96;          // B*T

constexpr int WSTRIDE = 68;      // weight row stride (floats), 16B-aligned

constexpr int SW_OFF = 0;
constexpr int SW_SZ  = 3 * HD * WSTRIDE;    // 3264
constexpr int SQ_OFF = SW_OFF + SW_SZ;      // 3264
constexpr int SQ_SZ  = N * HD;              // 8192
constexpr int SK_OFF = SQ_OFF + SQ_SZ;      // 11456
constexpr int SK_SZ  = N * HD;              // 8192 (16-float rows, XOR chunk-swizzled)
constexpr int SV_OFF = SK_OFF + SK_SZ;      // 19648
constexpr int SV_SZ  = N * HD;              // 8192

constexpr int CLS_OFF    = SK_OFF;          // overlay cls_map onto dead K/V
constexpr int CLS_STRIDE = 520;             // 8-float pad -> conflict-free pooling reads
constexpr int CLS_END    = CLS_OFF + C * CLS_STRIDE;          // 28096
constexpr int KV_END     = SV_OFF + SV_SZ;                    // 27840
constexpr int SMEM_FLOATS = (CLS_END > KV_END) ? CLS_END : KV_END;  // 28096 -> ~110KB
}

// ---- packed fp32x2 helpers (Blackwell FFMA2; ptxas never emits from C++) ----
__device__ __forceinline__ unsigned long long f2_pack(float lo, float hi) {
    unsigned long long r;
    asm("mov.b64 %0, {%1, %2};" : "=l"(r) : "f"(lo), "f"(hi));
    return r;
}
__device__ __forceinline__ void f2_unpack(unsigned long long v, float& lo, float& hi) {
    asm("mov.b64 {%0, %1}, %2;" : "=f"(lo), "=f"(hi) : "l"(v));
}
__device__ __forceinline__ unsigned long long f2_mul(unsigned long long a, unsigned long long b) {
    unsigned long long d;
    asm("mul.rn.f32x2 %0, %1, %2;" : "=l"(d) : "l"(a), "l"(b));
    return d;
}
__device__ __forceinline__ unsigned long long f2_fma(unsigned long long a, unsigned long long b,
                                                     unsigned long long c) {
    unsigned long long d;
    asm("fma.rn.f32x2 %0, %1, %2, %3;" : "=l"(d) : "l"(a), "l"(b), "l"(c));
    return d;
}
__device__ __forceinline__ float fast_ex2(float x) {
    float r;
    asm("ex2.approx.f32 %0, %1;" : "=f"(r) : "f"(x));
    return r;
}

__global__ __launch_bounds__(THREADS, 1)
void spatial_attn_kernel(const float* __restrict__ x,
                         const float* __restrict__ cls,
                         const float* __restrict__ Wq,
                         const float* __restrict__ Wk,
                         const float* __restrict__ Wv,
                         float* __restrict__ out) {
    extern __shared__ float smem[];

    const int blk = blockIdx.x;
    const int h   = blk & (NH - 1);
    const int bt  = blk >> 3;
    const float* xg   = x   + (size_t)bt * N * D;
    const float* clsg = cls + (size_t)bt * C * N;

    const int tid  = threadIdx.x;
    const int lane = tid & 31;
    const int wid  = tid >> 5;      // 0..7

    // ---- stage this head's weights into smem ----
    for (int idx = tid; idx < 3 * HD * D; idx += THREADS) {
        const int kind = idx >> 10;
        const int rem  = idx & 1023;
        const int e    = rem >> 6;
        const int d    = rem & 63;
        const float* Wsrc = (kind == 0) ? Wq : (kind == 1) ? Wk : Wv;
        smem[SW_OFF + kind * HD * WSTRIDE + e * WSTRIDE + d] = Wsrc[(h * HD + e) * D + d];
    }
    __syncthreads();

    // ---- projection: warp owns rows [wid*64, wid*64+64); x via broadcast LDG ----
    const int e    = lane & 15;
    const int half = lane >> 4;
    const float* sWq = smem + SW_OFF + 0 * HD * WSTRIDE + e * WSTRIDE;
    const float* sWk = smem + SW_OFF + 1 * HD * WSTRIDE + e * WSTRIDE;
    const float* sWv = smem + SW_OFF + 2 * HD * WSTRIDE + e * WSTRIDE;

    #pragma unroll
    for (int iter = 0; iter < 2; iter++) {
        const int rbase = wid * 64 + iter * 32 + half;   // rows rbase + 2r
        unsigned long long aq2[16], ak2[16], av2[16];
        #pragma unroll
        for (int r = 0; r < 16; r++) { aq2[r] = 0ULL; ak2[r] = 0ULL; av2[r] = 0ULL; }

        #pragma unroll 4
        for (int d4 = 0; d4 < 16; d4++) {
            const ulonglong2 wq2 = *reinterpret_cast<const ulonglong2*>(sWq + d4 * 4);
            const ulonglong2 wk2 = *reinterpret_cast<const ulonglong2*>(sWk + d4 * 4);
            const ulonglong2 wv2 = *reinterpret_cast<const ulonglong2*>(sWv + d4 * 4);
            #pragma unroll
            for (int r = 0; r < 16; r++) {
                const ulonglong2 x2 = *reinterpret_cast<const ulonglong2*>(
                    xg + (rbase + 2 * r) * D + d4 * 4);
                aq2[r] = f2_fma(x2.x, wq2.x, aq2[r]);
                aq2[r] = f2_fma(x2.y, wq2.y, aq2[r]);
                ak2[r] = f2_fma(x2.x, wk2.x, ak2[r]);
                ak2[r] = f2_fma(x2.y, wk2.y, ak2[r]);
                av2[r] = f2_fma(x2.x, wv2.x, av2[r]);
                av2[r] = f2_fma(x2.y, wv2.y, av2[r]);
            }
        }
        #pragma unroll
        for (int r = 0; r < 16; r++) {
            const int gr  = rbase + 2 * r;
            const int swz = (gr >> 1) & 3;                       // store-side XOR chunk swizzle
            const int pos = (((e >> 2) ^ swz) << 2) + (e & 3);
            float lo, hi;
            f2_unpack(aq2[r], lo, hi);
            smem[SQ_OFF + gr * HD + e]   = (lo + hi) * SCALE_EX2; // Q unswizzled, scale folded
            f2_unpack(ak2[r], lo, hi);
            smem[SK_OFF + gr * HD + pos] = lo + hi;
            f2_unpack(av2[r], lo, hi);
            smem[SV_OFF + gr * HD + pos] = lo + hi;
        }
    }
    __syncthreads();

    // ---- fused attention: per group of 4 query rows, single pass over keys ----
    // lane's key rows m = i*32+lane all share chunk swizzle ((m>>1)&3) = (lane>>1)&3
    const int swz = (lane >> 1) & 3;
    const int o0 = ((0 ^ swz) << 2);
    const int o1 = ((1 ^ swz) << 2);
    const int o2 = ((2 ^ swz) << 2);
    const int o3 = ((3 ^ swz) << 2);

    for (int g = 0; g < 16; g++) {
        const int n0 = wid * 64 + g * 4;

        // q: 4 rows x 16 dims (broadcast loads, unswizzled)
        ulonglong2 qv[4][4];
        #pragma unroll
        for (int r = 0; r < 4; r++)
            #pragma unroll
            for (int c = 0; c < 4; c++)
                qv[r][c] = *reinterpret_cast<const ulonglong2*>(
                    smem + SQ_OFF + (n0 + r) * HD + c * 4);

        unsigned long long acc[4][8];
        #pragma unroll
        for (int r = 0; r < 4; r++)
            #pragma unroll
            for (int j = 0; j < 8; j++) acc[r][j] = 0ULL;
        float ssum[4] = {0.f, 0.f, 0.f, 0.f};

        #pragma unroll 2
        for (int i = 0; i < 16; i++) {
            const float* kr = smem + SK_OFF + (i * 32 + lane) * HD;
            const float* vr = smem + SV_OFF + (i * 32 + lane) * HD;
            const ulonglong2 kc0 = *reinterpret_cast<const ulonglong2*>(kr + o0);
            const ulonglong2 kc1 = *reinterpret_cast<const ulonglong2*>(kr + o1);
            const ulonglong2 kc2 = *reinterpret_cast<const ulonglong2*>(kr + o2);
            const ulonglong2 kc3 = *reinterpret_cast<const ulonglong2*>(kr + o3);
            const ulonglong2 vc0 = *reinterpret_cast<const ulonglong2*>(vr + o0);
            const ulonglong2 vc1 = *reinterpret_cast<const ulonglong2*>(vr + o1);
            const ulonglong2 vc2 = *reinterpret_cast<const ulonglong2*>(vr + o2);
            const ulonglong2 vc3 = *reinterpret_cast<const ulonglong2*>(vr + o3);

            #pragma unroll
            for (int r = 0; r < 4; r++) {
                unsigned long long t = f2_mul(qv[r][0].x, kc0.x);
                t = f2_fma(qv[r][0].y, kc0.y, t);
                t = f2_fma(qv[r][1].x, kc1.x, t);
                t = f2_fma(qv[r][1].y, kc1.y, t);
                t = f2_fma(qv[r][2].x, kc2.x, t);
                t = f2_fma(qv[r][2].y, kc2.y, t);
                t = f2_fma(qv[r][3].x, kc3.x, t);
                t = f2_fma(qv[r][3].y, kc3.y, t);
                float lo, hi;
                f2_unpack(t, lo, hi);
                const float p = fast_ex2(lo + hi);   // exp(0.25*qk) via folded log2e
                ssum[r] += p;
                const unsigned long long p2 = f2_pack(p, p);
                acc[r][0] = f2_fma(p2, vc0.x, acc[r][0]);
                acc[r][1] = f2_fma(p2, vc0.y, acc[r][1]);
                acc[r][2] = f2_fma(p2, vc1.x, acc[r][2]);
                acc[r][3] = f2_fma(p2, vc1.y, acc[r][3]);
                acc[r][4] = f2_fma(p2, vc2.x, acc[r][4]);
                acc[r][5] = f2_fma(p2, vc2.y, acc[r][5]);
                acc[r][6] = f2_fma(p2, vc3.x, acc[r][6]);
                acc[r][7] = f2_fma(p2, vc3.y, acc[r][7]);
            }
        }

        // per-row normalization constants
        float inv[4];
        #pragma unroll
        for (int r = 0; r < 4; r++) {
            float ss = ssum[r];
            #pragma unroll
            for (int off = 16; off > 0; off >>= 1)
                ss += __shfl_xor_sync(0xffffffffu, ss, off);
            inv[r] = __frcp_rn(ss);
        }

        // log-fold reduce: 16 dims over 32 lanes (16 shfl/row); write sx into SQ
        const bool s4 = (lane & 16) != 0;
        const bool s3 = (lane & 8)  != 0;
        const bool s2 = (lane & 4)  != 0;
        const bool s1 = (lane & 2)  != 0;
        #pragma unroll
        for (int r = 0; r < 4; r++) {
            float a[16];
            #pragma unroll
            for (int j = 0; j < 8; j++)
                f2_unpack(acc[r][j], a[2 * j], a[2 * j + 1]);
            #pragma unroll
            for (int j = 0; j < 8; j++) {
                const float keepv = s4 ? a[8 + j] : a[j];
                const float sendv = s4 ? a[j] : a[8 + j];
                a[j] = keepv + __shfl_xor_sync(0xffffffffu, sendv, 16);
            }
            #pragma unroll
            for (int j = 0; j < 4; j++) {
                const float keepv = s3 ? a[4 + j] : a[j];
                const float sendv = s3 ? a[j] : a[4 + j];
                a[j] = keepv + __shfl_xor_sync(0xffffffffu, sendv, 8);
            }
            #pragma unroll
            for (int j = 0; j < 2; j++) {
                const float keepv = s2 ? a[2 + j] : a[j];
                const float sendv = s2 ? a[j] : a[2 + j];
                a[j] = keepv + __shfl_xor_sync(0xffffffffu, sendv, 4);
            }
            {
                const float keepv = s1 ? a[1] : a[0];
                const float sendv = s1 ? a[0] : a[1];
                a[0] = keepv + __shfl_xor_sync(0xffffffffu, sendv, 2);
            }
            a[0] += __shfl_xor_sync(0xffffffffu, a[0], 1);
            if ((lane & 1) == 0) {
                const int dmap = ((lane >> 4) & 1) * 8 + ((lane >> 3) & 1) * 4
                               + ((lane >> 2) & 1) * 2 + ((lane >> 1) & 1);
                smem[SQ_OFF + (n0 + r) * HD + dmap] = a[0] * inv[r];
            }
        }
    }
    __syncthreads();

    // ---- stage cls_map into dead K/V smem (padded stride) ----
    {
        const float4* src = reinterpret_cast<const float4*>(clsg);
        #pragma unroll
        for (int i = tid; i < C * N / 4; i += THREADS) {
            const int c  = i >> 7;
            const int n4 = i & 127;
            *reinterpret_cast<float4*>(smem + CLS_OFF + c * CLS_STRIDE + n4 * 4) = src[i];
        }
    }
    __syncthreads();

    // ---- cls pooling: thread (c = tid>>3, dims 2*(tid&7), +1) ----
    {
        const int c  = tid >> 3;
        const int d0 = (tid & 7) * 2;
        const float* pc  = smem + CLS_OFF + c * CLS_STRIDE;
        const float* psx = smem + SQ_OFF + d0;
        float a0 = 0.f, a1 = 0.f, a2 = 0.f, a3 = 0.f;
        #pragma unroll 4
        for (int n = 0; n < N; n += 4) {
            const float4 cl = *reinterpret_cast<const float4*>(pc + n);
            const float2 s0 = *reinterpret_cast<const float2*>(psx + (n + 0) * HD);
            const float2 s1v = *reinterpret_cast<const float2*>(psx + (n + 1) * HD);
            const float2 s2v = *reinterpret_cast<const float2*>(psx + (n + 2) * HD);
            const float2 s3v = *reinterpret_cast<const float2*>(psx + (n + 3) * HD);
            a0 = fmaf(cl.x, s0.x, a0);   a1 = fmaf(cl.x, s0.y, a1);
            a2 = fmaf(cl.y, s1v.x, a2);  a3 = fmaf(cl.y, s1v.y, a3);
            a0 = fmaf(cl.z, s2v.x, a0);  a1 = fmaf(cl.z, s2v.y, a1);
            a2 = fmaf(cl.w, s3v.x, a2);  a3 = fmaf(cl.w, s3v.y, a3);
        }
        float2 res;
        res.x = a0 + a2;
        res.y = a1 + a3;
        *reinterpret_cast<float2*>(out + ((size_t)bt * C + c) * HID + h * HD + d0) = res;
    }
}

extern "C" void kernel_launch(void* const* d_in, const int* in_sizes, int n_in,
                              void* d_out, int out_size) {
    const float* x   = (const float*)d_in[0];
    const float* cls = (const float*)d_in[1];
    const float* Wq  = (const float*)d_in[2];
    const float* Wk  = (const float*)d_in[3];
    const float* Wv  = (const float*)d_in[4];
    float* out = (float*)d_out;

    const size_t smem_bytes = (size_t)SMEM_FLOATS * sizeof(float);  // ~110 KB
    cudaFuncSetAttribute(spatial_attn_kernel,
                         cudaFuncAttributeMaxDynamicSharedMemorySize,
                         (int)smem_bytes);
    spatial_attn_kernel<<<NBT * NH, THREADS, smem_bytes>>>(x, cls, Wq, Wk, Wv, out);
}

// round 8
// speedup vs baseline: 1.3366x; 1.0001x over previous
#include <cuda_runtime.h>

namespace {
constexpr int N   = 512;
constexpr int D   = 64;
constexpr int C   = 32;
constexpr int HID = 128;
constexpr int NH  = 8;
constexpr int HD  = 16;
// fold 0.25 (head_dim^-0.5) and log2(e) into Q so softmax uses raw EX2
constexpr float SCALE_EX2 = 0.25f * 1.4426950408889634f;
constexpr int THREADS = 256;
constexpr int NBT = 96;          // B*T

constexpr int WSTRIDE = 68;      // weight row stride (floats), 16B-aligned

constexpr int SW_OFF = 0;
constexpr int SW_SZ  = 3 * HD * WSTRIDE;    // 3264
constexpr int SQ_OFF = SW_OFF + SW_SZ;      // 3264
constexpr int SQ_SZ  = N * HD;              // 8192
constexpr int SK_OFF = SQ_OFF + SQ_SZ;      // 11456
constexpr int SK_SZ  = N * HD;              // 8192 (16-float rows, XOR chunk-swizzled)
constexpr int SV_OFF = SK_OFF + SK_SZ;      // 19648
constexpr int SV_SZ  = N * HD;              // 8192

constexpr int CLS_OFF    = SK_OFF;          // overlay cls_map onto dead K/V
constexpr int CLS_STRIDE = 520;             // 8-float pad -> conflict-free pooling reads
constexpr int CLS_END    = CLS_OFF + C * CLS_STRIDE;          // 28096
constexpr int KV_END     = SV_OFF + SV_SZ;                    // 27840
constexpr int SMEM_FLOATS = (CLS_END > KV_END) ? CLS_END : KV_END;  // 28096 -> ~110KB
}

// ---- packed fp32x2 helpers (Blackwell FFMA2; ptxas never emits from C++) ----
__device__ __forceinline__ unsigned long long f2_pack(float lo, float hi) {
    unsigned long long r;
    asm("mov.b64 %0, {%1, %2};" : "=l"(r) : "f"(lo), "f"(hi));
    return r;
}
__device__ __forceinline__ void f2_unpack(unsigned long long v, float& lo, float& hi) {
    asm("mov.b64 {%0, %1}, %2;" : "=f"(lo), "=f"(hi) : "l"(v));
}
__device__ __forceinline__ unsigned long long f2_mul(unsigned long long a, unsigned long long b) {
    unsigned long long d;
    asm("mul.rn.f32x2 %0, %1, %2;" : "=l"(d) : "l"(a), "l"(b));
    return d;
}
__device__ __forceinline__ unsigned long long f2_fma(unsigned long long a, unsigned long long b,
                                                     unsigned long long c) {
    unsigned long long d;
    asm("fma.rn.f32x2 %0, %1, %2, %3;" : "=l"(d) : "l"(a), "l"(b), "l"(c));
    return d;
}
__device__ __forceinline__ float fast_ex2(float x) {
    float r;
    asm("ex2.approx.f32 %0, %1;" : "=f"(r) : "f"(x));
    return r;
}

__global__ __launch_bounds__(THREADS, 1)
void spatial_attn_kernel(const float* __restrict__ x,
                         const float* __restrict__ cls,
                         const float* __restrict__ Wq,
                         const float* __restrict__ Wk,
                         const float* __restrict__ Wv,
                         float* __restrict__ out) {
    extern __shared__ float smem[];

    const int blk = blockIdx.x;
    const int h   = blk & (NH - 1);
    const int bt  = blk >> 3;
    const float* xg   = x   + (size_t)bt * N * D;
    const float* clsg = cls + (size_t)bt * C * N;

    const int tid  = threadIdx.x;
    const int lane = tid & 31;
    const int wid  = tid >> 5;      // 0..7

    // ---- stage this head's weights into smem ----
    for (int idx = tid; idx < 3 * HD * D; idx += THREADS) {
        const int kind = idx >> 10;
        const int rem  = idx & 1023;
        const int e    = rem >> 6;
        const int d    = rem & 63;
        const float* Wsrc = (kind == 0) ? Wq : (kind == 1) ? Wk : Wv;
        smem[SW_OFF + kind * HD * WSTRIDE + e * WSTRIDE + d] = Wsrc[(h * HD + e) * D + d];
    }
    __syncthreads();

    // ---- projection: warp owns rows [wid*64, wid*64+64); x via broadcast LDG ----
    const int e    = lane & 15;
    const int half = lane >> 4;
    const float* sWq = smem + SW_OFF + 0 * HD * WSTRIDE + e * WSTRIDE;
    const float* sWk = smem + SW_OFF + 1 * HD * WSTRIDE + e * WSTRIDE;
    const float* sWv = smem + SW_OFF + 2 * HD * WSTRIDE + e * WSTRIDE;

    #pragma unroll
    for (int iter = 0; iter < 2; iter++) {
        const int rbase = wid * 64 + iter * 32 + half;   // rows rbase + 2r
        unsigned long long aq2[16], ak2[16], av2[16];
        #pragma unroll
        for (int r = 0; r < 16; r++) { aq2[r] = 0ULL; ak2[r] = 0ULL; av2[r] = 0ULL; }

        #pragma unroll 4
        for (int d4 = 0; d4 < 16; d4++) {
            const ulonglong2 wq2 = *reinterpret_cast<const ulonglong2*>(sWq + d4 * 4);
            const ulonglong2 wk2 = *reinterpret_cast<const ulonglong2*>(sWk + d4 * 4);
            const ulonglong2 wv2 = *reinterpret_cast<const ulonglong2*>(sWv + d4 * 4);
            #pragma unroll
            for (int r = 0; r < 16; r++) {
                const ulonglong2 x2 = *reinterpret_cast<const ulonglong2*>(
                    xg + (rbase + 2 * r) * D + d4 * 4);
                aq2[r] = f2_fma(x2.x, wq2.x, aq2[r]);
                aq2[r] = f2_fma(x2.y, wq2.y, aq2[r]);
                ak2[r] = f2_fma(x2.x, wk2.x, ak2[r]);
                ak2[r] = f2_fma(x2.y, wk2.y, ak2[r]);
                av2[r] = f2_fma(x2.x, wv2.x, av2[r]);
                av2[r] = f2_fma(x2.y, wv2.y, av2[r]);
            }
        }
        #pragma unroll
        for (int r = 0; r < 16; r++) {
            const int gr  = rbase + 2 * r;
            const int swz = (gr >> 1) & 3;                       // store-side XOR chunk swizzle
            const int pos = (((e >> 2) ^ swz) << 2) + (e & 3);
            float lo, hi;
            f2_unpack(aq2[r], lo, hi);
            smem[SQ_OFF + gr * HD + e]   = (lo + hi) * SCALE_EX2; // Q unswizzled, scale folded
            f2_unpack(ak2[r], lo, hi);
            smem[SK_OFF + gr * HD + pos] = lo + hi;
            f2_unpack(av2[r], lo, hi);
            smem[SV_OFF + gr * HD + pos] = lo + hi;
        }
    }
    __syncthreads();

    // ---- fused attention: per group of 4 query rows, single pass over keys ----
    // lane's key rows m = i*32+lane all share chunk swizzle ((m>>1)&3) = (lane>>1)&3
    const int swz = (lane >> 1) & 3;
    const int o0 = ((0 ^ swz) << 2);
    const int o1 = ((1 ^ swz) << 2);
    const int o2 = ((2 ^ swz) << 2);
    const int o3 = ((3 ^ swz) << 2);

    for (int g = 0; g < 16; g++) {
        const int n0 = wid * 64 + g * 4;

        // q: 4 rows x 16 dims (broadcast loads, unswizzled)
        ulonglong2 qv[4][4];
        #pragma unroll
        for (int r = 0; r < 4; r++)
            #pragma unroll
            for (int c = 0; c < 4; c++)
                qv[r][c] = *reinterpret_cast<const ulonglong2*>(
                    smem + SQ_OFF + (n0 + r) * HD + c * 4);

        unsigned long long acc[4][8];
        #pragma unroll
        for (int r = 0; r < 4; r++)
            #pragma unroll
            for (int j = 0; j < 8; j++) acc[r][j] = 0ULL;
        float ssum[4] = {0.f, 0.f, 0.f, 0.f};

        #pragma unroll 2
        for (int i = 0; i < 16; i++) {
            const float* kr = smem + SK_OFF + (i * 32 + lane) * HD;
            const float* vr = smem + SV_OFF + (i * 32 + lane) * HD;
            const ulonglong2 kc0 = *reinterpret_cast<const ulonglong2*>(kr + o0);
            const ulonglong2 kc1 = *reinterpret_cast<const ulonglong2*>(kr + o1);
            const ulonglong2 kc2 = *reinterpret_cast<const ulonglong2*>(kr + o2);
            const ulonglong2 kc3 = *reinterpret_cast<const ulonglong2*>(kr + o3);
            const ulonglong2 vc0 = *reinterpret_cast<const ulonglong2*>(vr + o0);
            const ulonglong2 vc1 = *reinterpret_cast<const ulonglong2*>(vr + o1);
            const ulonglong2 vc2 = *reinterpret_cast<const ulonglong2*>(vr + o2);
            const ulonglong2 vc3 = *reinterpret_cast<const ulonglong2*>(vr + o3);

            #pragma unroll
            for (int r = 0; r < 4; r++) {
                unsigned long long t = f2_mul(qv[r][0].x, kc0.x);
                t = f2_fma(qv[r][0].y, kc0.y, t);
                t = f2_fma(qv[r][1].x, kc1.x, t);
                t = f2_fma(qv[r][1].y, kc1.y, t);
                t = f2_fma(qv[r][2].x, kc2.x, t);
                t = f2_fma(qv[r][2].y, kc2.y, t);
                t = f2_fma(qv[r][3].x, kc3.x, t);
                t = f2_fma(qv[r][3].y, kc3.y, t);
                float lo, hi;
                f2_unpack(t, lo, hi);
                const float p = fast_ex2(lo + hi);   // exp(0.25*qk) via folded log2e
                ssum[r] += p;
                const unsigned long long p2 = f2_pack(p, p);
                acc[r][0] = f2_fma(p2, vc0.x, acc[r][0]);
                acc[r][1] = f2_fma(p2, vc0.y, acc[r][1]);
                acc[r][2] = f2_fma(p2, vc1.x, acc[r][2]);
                acc[r][3] = f2_fma(p2, vc1.y, acc[r][3]);
                acc[r][4] = f2_fma(p2, vc2.x, acc[r][4]);
                acc[r][5] = f2_fma(p2, vc2.y, acc[r][5]);
                acc[r][6] = f2_fma(p2, vc3.x, acc[r][6]);
                acc[r][7] = f2_fma(p2, vc3.y, acc[r][7]);
            }
        }

        // per-row normalization constants
        float inv[4];
        #pragma unroll
        for (int r = 0; r < 4; r++) {
            float ss = ssum[r];
            #pragma unroll
            for (int off = 16; off > 0; off >>= 1)
                ss += __shfl_xor_sync(0xffffffffu, ss, off);
            inv[r] = __frcp_rn(ss);
        }

        // log-fold reduce: 16 dims over 32 lanes (16 shfl/row); write sx into SQ
        const bool s4 = (lane & 16) != 0;
        const bool s3 = (lane & 8)  != 0;
        const bool s2 = (lane & 4)  != 0;
        const bool s1 = (lane & 2)  != 0;
        #pragma unroll
        for (int r = 0; r < 4; r++) {
            float a[16];
            #pragma unroll
            for (int j = 0; j < 8; j++)
                f2_unpack(acc[r][j], a[2 * j], a[2 * j + 1]);
            #pragma unroll
            for (int j = 0; j < 8; j++) {
                const float keepv = s4 ? a[8 + j] : a[j];
                const float sendv = s4 ? a[j] : a[8 + j];
                a[j] = keepv + __shfl_xor_sync(0xffffffffu, sendv, 16);
            }
            #pragma unroll
            for (int j = 0; j < 4; j++) {
                const float keepv = s3 ? a[4 + j] : a[j];
                const float sendv = s3 ? a[j] : a[4 + j];
                a[j] = keepv + __shfl_xor_sync(0xffffffffu, sendv, 8);
            }
            #pragma unroll
            for (int j = 0; j < 2; j++) {
                const float keepv = s2 ? a[2 + j] : a[j];
                const float sendv = s2 ? a[j] : a[2 + j];
                a[j] = keepv + __shfl_xor_sync(0xffffffffu, sendv, 4);
            }
            {
                const float keepv = s1 ? a[1] : a[0];
                const float sendv = s1 ? a[0] : a[1];
                a[0] = keepv + __shfl_xor_sync(0xffffffffu, sendv, 2);
            }
            a[0] += __shfl_xor_sync(0xffffffffu, a[0], 1);
            if ((lane & 1) == 0) {
                const int dmap = ((lane >> 4) & 1) * 8 + ((lane >> 3) & 1) * 4
                               + ((lane >> 2) & 1) * 2 + ((lane >> 1) & 1);
                smem[SQ_OFF + (n0 + r) * HD + dmap] = a[0] * inv[r];
            }
        }
    }
    __syncthreads();

    // ---- stage cls_map into dead K/V smem (padded stride) ----
    {
        const float4* src = reinterpret_cast<const float4*>(clsg);
        #pragma unroll
        for (int i = tid; i < C * N / 4; i += THREADS) {
            const int c  = i >> 7;
            const int n4 = i & 127;
            *reinterpret_cast<float4*>(smem + CLS_OFF + c * CLS_STRIDE + n4 * 4) = src[i];
        }
    }
    __syncthreads();

    // ---- cls pooling: thread (c = tid>>3, dims 2*(tid&7), +1) ----
    {
        const int c  = tid >> 3;
        const int d0 = (tid & 7) * 2;
        const float* pc  = smem + CLS_OFF + c * CLS_STRIDE;
        const float* psx = smem + SQ_OFF + d0;
        float a0 = 0.f, a1 = 0.f, a2 = 0.f, a3 = 0.f;
        #pragma unroll 4
        for (int n = 0; n < N; n += 4) {
            const float4 cl = *reinterpret_cast<const float4*>(pc + n);
            const float2 s0 = *reinterpret_cast<const float2*>(psx + (n + 0) * HD);
            const float2 s1v = *reinterpret_cast<const float2*>(psx + (n + 1) * HD);
            const float2 s2v = *reinterpret_cast<const float2*>(psx + (n + 2) * HD);
            const float2 s3v = *reinterpret_cast<const float2*>(psx + (n + 3) * HD);
            a0 = fmaf(cl.x, s0.x, a0);   a1 = fmaf(cl.x, s0.y, a1);
            a2 = fmaf(cl.y, s1v.x, a2);  a3 = fmaf(cl.y, s1v.y, a3);
            a0 = fmaf(cl.z, s2v.x, a0);  a1 = fmaf(cl.z, s2v.y, a1);
            a2 = fmaf(cl.w, s3v.x, a2);  a3 = fmaf(cl.w, s3v.y, a3);
        }
        float2 res;
        res.x = a0 + a2;
        res.y = a1 + a3;
        *reinterpret_cast<float2*>(out + ((size_t)bt * C + c) * HID + h * HD + d0) = res;
    }
}

extern "C" void kernel_launch(void* const* d_in, const int* in_sizes, int n_in,
                              void* d_out, int out_size) {
    const float* x   = (const float*)d_in[0];
    const float* cls = (const float*)d_in[1];
    const float* Wq  = (const float*)d_in[2];
    const float* Wk  = (const float*)d_in[3];
    const float* Wv  = (const float*)d_in[4];
    float* out = (float*)d_out;

    const size_t smem_bytes = (size_t)SMEM_FLOATS * sizeof(float);  // ~110 KB
    cudaFuncSetAttribute(spatial_attn_kernel,
                         cudaFuncAttributeMaxDynamicSharedMemorySize,
                         (int)smem_bytes);
    spatial_attn_kernel<<<NBT * NH, THREADS, smem_bytes>>>(x, cls, Wq, Wk, Wv, out);
}

// round 10
// speedup vs baseline: 3.3407x; 2.4993x over previous
#include <cuda_runtime.h>
#include <stdint.h>

namespace {
constexpr int N   = 512;
constexpr int D   = 64;
constexpr int C   = 32;
constexpr int HID = 128;
constexpr int NH  = 8;
constexpr int HD  = 16;
constexpr float SCALE_EX2 = 0.25f * 1.4426950408889634f;  // head_dim^-0.5 * log2(e)
constexpr float NEG_BIAS  = -8.0f;                         // fp16 overflow guard (cancels)
constexpr int THREADS = 512;
constexpr int NBT = 96;
constexpr int WSTRIDE = 68;

// smem byte offsets
constexpr int OFF_SW = 0;                       // weights f32: 3*16*68*4 = 13056
constexpr int OFF_Q  = 13056;                   // Q fp16 [512][16], row stride 32B
constexpr int OFF_K  = OFF_Q + 512 * 32;        // K fp16 [512][16], row stride 48B (pad)
constexpr int OFF_V  = OFF_K + 512 * 48;        // V fp16 [512][16], row stride 48B
constexpr int OFF_SX = OFF_V + 512 * 48;        // sx f32 [512][20] (pad stride 80B)
constexpr int SMEM_BYTES = OFF_SX + 512 * 80;   // 119552 B

constexpr int OFF_CLS = 0;                      // overlay cls over dead W/Q/K/V
constexpr int CLS_STRIDE = 520;                 // floats
constexpr uint32_t ONES2 = 0x3C003C00u;         // fp16x2 {1,1}
}

__device__ __forceinline__ uint32_t s2u(const void* p) {
    uint32_t a;
    asm("{ .reg .u64 t; cvta.to.shared.u64 t, %1; cvt.u32.u64 %0, t; }" : "=r"(a) : "l"(p));
    return a;
}
__device__ __forceinline__ unsigned long long f2_fma(unsigned long long a, unsigned long long b,
                                                     unsigned long long c) {
    unsigned long long d;
    asm("fma.rn.f32x2 %0, %1, %2, %3;" : "=l"(d) : "l"(a), "l"(b), "l"(c));
    return d;
}
__device__ __forceinline__ void f2_unpack(unsigned long long v, float& lo, float& hi) {
    asm("mov.b64 {%0, %1}, %2;" : "=f"(lo), "=f"(hi) : "l"(v));
}
__device__ __forceinline__ float fast_ex2(float x) {
    float r; asm("ex2.approx.f32 %0, %1;" : "=f"(r) : "f"(x)); return r;
}
__device__ __forceinline__ uint16_t h_of(float v) {
    uint16_t r; asm("cvt.rn.f16.f32 %0, %1;" : "=h"(r) : "f"(v)); return r;
}
__device__ __forceinline__ uint32_t h2sat(float lo, float hi) {
    uint32_t r;
    asm("cvt.rn.satfinite.f16x2.f32 %0, %1, %2;" : "=r"(r) : "f"(hi), "f"(lo));
    return r;
}
__device__ __forceinline__ void ldm_x4(uint32_t r[4], uint32_t addr) {
    asm volatile("ldmatrix.sync.aligned.m8n8.x4.shared.b16 {%0,%1,%2,%3}, [%4];"
                 : "=r"(r[0]), "=r"(r[1]), "=r"(r[2]), "=r"(r[3]) : "r"(addr));
}
__device__ __forceinline__ void ldm_x4t(uint32_t r[4], uint32_t addr) {
    asm volatile("ldmatrix.sync.aligned.m8n8.x4.trans.shared.b16 {%0,%1,%2,%3}, [%4];"
                 : "=r"(r[0]), "=r"(r[1]), "=r"(r[2]), "=r"(r[3]) : "r"(addr));
}
__device__ __forceinline__ void mma16816(float* d,
                                         const uint32_t* a, uint32_t b0, uint32_t b1,
                                         float c0, float c1, float c2, float c3) {
    asm volatile("mma.sync.aligned.m16n8k16.row.col.f32.f16.f16.f32 "
                 "{%0,%1,%2,%3}, {%4,%5,%6,%7}, {%8,%9}, {%10,%11,%12,%13};"
                 : "=f"(d[0]), "=f"(d[1]), "=f"(d[2]), "=f"(d[3])
                 : "r"(a[0]), "r"(a[1]), "r"(a[2]), "r"(a[3]), "r"(b0), "r"(b1),
                   "f"(c0), "f"(c1), "f"(c2), "f"(c3));
}

__global__ __launch_bounds__(THREADS, 1)
void spatial_attn_mma(const float* __restrict__ x, const float* __restrict__ cls,
                      const float* __restrict__ Wq, const float* __restrict__ Wk,
                      const float* __restrict__ Wv, float* __restrict__ out) {
    extern __shared__ char smem[];
    float* smf = reinterpret_cast<float*>(smem);
    const uint32_t sbase = s2u(smem);

    const int blk = blockIdx.x, h = blk & (NH - 1), bt = blk >> 3;
    const float* xg   = x + (size_t)bt * N * D;
    const float* clsg = cls + (size_t)bt * C * N;
    const int tid = threadIdx.x, lane = tid & 31, wid = tid >> 5;   // 16 warps

    // ---- stage this head's weights (fp32) ----
    float* sW = smf + OFF_SW / 4;
    for (int idx = tid; idx < 3 * HD * D; idx += THREADS) {
        const int kind = idx >> 10, rem = idx & 1023, e = rem >> 6, d = rem & 63;
        const float* Ws = (kind == 0) ? Wq : (kind == 1) ? Wk : Wv;
        sW[kind * HD * WSTRIDE + e * WSTRIDE + d] = Ws[(h * HD + e) * D + d];
    }
    __syncthreads();

    // ---- projection: fp32 SIMT, fp16 outputs (Q scaled by 0.25*log2e) ----
    {
        const int e = lane & 15, half = lane >> 4;
        const float* wq = sW + 0 * HD * WSTRIDE + e * WSTRIDE;
        const float* wk = sW + 1 * HD * WSTRIDE + e * WSTRIDE;
        const float* wv = sW + 2 * HD * WSTRIDE + e * WSTRIDE;
        #pragma unroll
        for (int iter = 0; iter < 2; iter++) {
            const int rbase = wid * 32 + iter * 16 + half;
            unsigned long long aq2[8], ak2[8], av2[8];
            #pragma unroll
            for (int r = 0; r < 8; r++) { aq2[r] = 0ULL; ak2[r] = 0ULL; av2[r] = 0ULL; }
            #pragma unroll 4
            for (int d4 = 0; d4 < 16; d4++) {
                const ulonglong2 wq2 = *reinterpret_cast<const ulonglong2*>(wq + d4 * 4);
                const ulonglong2 wk2 = *reinterpret_cast<const ulonglong2*>(wk + d4 * 4);
                const ulonglong2 wv2 = *reinterpret_cast<const ulonglong2*>(wv + d4 * 4);
                #pragma unroll
                for (int r = 0; r < 8; r++) {
                    const ulonglong2 x2 = *reinterpret_cast<const ulonglong2*>(
                        xg + (rbase + 2 * r) * D + d4 * 4);
                    aq2[r] = f2_fma(x2.x, wq2.x, aq2[r]);
                    aq2[r] = f2_fma(x2.y, wq2.y, aq2[r]);
                    ak2[r] = f2_fma(x2.x, wk2.x, ak2[r]);
                    ak2[r] = f2_fma(x2.y, wk2.y, ak2[r]);
                    av2[r] = f2_fma(x2.x, wv2.x, av2[r]);
                    av2[r] = f2_fma(x2.y, wv2.y, av2[r]);
                }
            }
            #pragma unroll
            for (int r = 0; r < 8; r++) {
                const int gr = rbase + 2 * r;
                float lo, hi;
                f2_unpack(aq2[r], lo, hi);
                *reinterpret_cast<uint16_t*>(smem + OFF_Q + gr * 32 + e * 2) =
                    h_of((lo + hi) * SCALE_EX2);
                f2_unpack(ak2[r], lo, hi);
                *reinterpret_cast<uint16_t*>(smem + OFF_K + gr * 48 + e * 2) = h_of(lo + hi);
                f2_unpack(av2[r], lo, hi);
                *reinterpret_cast<uint16_t*>(smem + OFF_V + gr * 48 + e * 2) = h_of(lo + hi);
            }
        }
    }
    __syncthreads();

    // ---- flash attention via mma.sync: warp owns rows [wid*32, wid*32+32) ----
    {
        const int rb = wid * 32;
        uint32_t qa[2][4];
        #pragma unroll
        for (int mt = 0; mt < 2; mt++)
            ldm_x4(qa[mt], sbase + OFF_Q + (uint32_t)(rb + mt * 16 + (lane & 15)) * 32u
                                 + (uint32_t)(lane >> 4) * 16u);

        float O[2][2][4], R[2][4];
        #pragma unroll
        for (int mt = 0; mt < 2; mt++) {
            #pragma unroll
            for (int nn = 0; nn < 2; nn++)
                #pragma unroll
                for (int j = 0; j < 4; j++) O[mt][nn][j] = 0.f;
            #pragma unroll
            for (int j = 0; j < 4; j++) R[mt][j] = 0.f;
        }

        const uint32_t koff = (uint32_t)(((lane & 7) + ((lane & 16) ? 8 : 0)) * 48
                                         + ((lane & 8) ? 16 : 0));
        const uint32_t voff = (uint32_t)(((lane & 7) + ((lane & 8) ? 8 : 0)) * 48
                                         + ((lane & 16) ? 16 : 0));

        #pragma unroll 4
        for (int kb = 0; kb < 32; kb++) {
            uint32_t kf[4], vf[4];
            ldm_x4 (kf, sbase + OFF_K + (uint32_t)kb * 768u + koff);
            ldm_x4t(vf, sbase + OFF_V + (uint32_t)kb * 768u + voff);

            #pragma unroll
            for (int mt = 0; mt < 2; mt++) {
                float s0[4], s1[4];
                mma16816(s0, qa[mt], kf[0], kf[1], NEG_BIAS, NEG_BIAS, NEG_BIAS, NEG_BIAS);
                mma16816(s1, qa[mt], kf[2], kf[3], NEG_BIAS, NEG_BIAS, NEG_BIAS, NEG_BIAS);
                uint32_t pa[4];
                pa[0] = h2sat(fast_ex2(s0[0]), fast_ex2(s0[1]));
                pa[1] = h2sat(fast_ex2(s0[2]), fast_ex2(s0[3]));
                pa[2] = h2sat(fast_ex2(s1[0]), fast_ex2(s1[1]));
                pa[3] = h2sat(fast_ex2(s1[2]), fast_ex2(s1[3]));
                mma16816(O[mt][0], pa, vf[0], vf[1],
                         O[mt][0][0], O[mt][0][1], O[mt][0][2], O[mt][0][3]);
                mma16816(O[mt][1], pa, vf[2], vf[3],
                         O[mt][1][0], O[mt][1][1], O[mt][1][2], O[mt][1][3]);
                mma16816(R[mt], pa, ONES2, ONES2,
                         R[mt][0], R[mt][1], R[mt][2], R[mt][3]);
            }
        }

        // normalize + write sx [512][20] f32
        float* sx = smf + OFF_SX / 4;
        const int g = lane >> 2, cq = (lane & 3) * 2;
        #pragma unroll
        for (int mt = 0; mt < 2; mt++) {
            const float inv0 = __frcp_rn(R[mt][0]);
            const float inv1 = __frcp_rn(R[mt][2]);
            const int row0 = rb + mt * 16 + g, row1 = row0 + 8;
            #pragma unroll
            for (int nn = 0; nn < 2; nn++) {
                float2 u0, u1;
                u0.x = O[mt][nn][0] * inv0; u0.y = O[mt][nn][1] * inv0;
                u1.x = O[mt][nn][2] * inv1; u1.y = O[mt][nn][3] * inv1;
                *reinterpret_cast<float2*>(sx + row0 * 20 + nn * 8 + cq) = u0;
                *reinterpret_cast<float2*>(sx + row1 * 20 + nn * 8 + cq) = u1;
            }
        }
    }
    __syncthreads();

    // ---- stage cls_map over dead W/Q/K/V ----
    {
        const float4* src = reinterpret_cast<const float4*>(clsg);
        float* cb = smf + OFF_CLS / 4;
        for (int i = tid; i < C * N / 4; i += THREADS) {
            const int c = i >> 7, n4 = i & 127;
            *reinterpret_cast<float4*>(cb + c * CLS_STRIDE + n4 * 4) = src[i];
        }
    }
    __syncthreads();

    // ---- cls pooling: thread (c = tid>>4, d = tid&15) ----
    {
        const int c = tid >> 4, d = tid & 15;
        const float* pc  = smf + OFF_CLS / 4 + c * CLS_STRIDE;
        const float* psx = smf + OFF_SX / 4 + d;
        float a0 = 0.f, a1 = 0.f, a2 = 0.f, a3 = 0.f;
        #pragma unroll 4
        for (int n = 0; n < N; n += 4) {
            const float4 cl = *reinterpret_cast<const float4*>(pc + n);
            a0 = fmaf(cl.x, psx[(n + 0) * 20], a0);
            a1 = fmaf(cl.y, psx[(n + 1) * 20], a1);
            a2 = fmaf(cl.z, psx[(n + 2) * 20], a2);
            a3 = fmaf(cl.w, psx[(n + 3) * 20], a3);
        }
        out[((size_t)bt * C + c) * HID + h * HD + d] = (a0 + a1) + (a2 + a3);
    }
}

extern "C" void kernel_launch(void* const* d_in, const int* in_sizes, int n_in,
                              void* d_out, int out_size) {
    const float* x   = (const float*)d_in[0];
    const float* cls = (const float*)d_in[1];
    const float* Wq  = (const float*)d_in[2];
    const float* Wk  = (const float*)d_in[3];
    const float* Wv  = (const float*)d_in[4];
    float* out = (float*)d_out;

    cudaFuncSetAttribute(spatial_attn_mma, cudaFuncAttributeMaxDynamicSharedMemorySize,
                         SMEM_BYTES);
    spatial_attn_mma<<<NBT * NH, THREADS, SMEM_BYTES>>>(x, cls, Wq, Wk, Wv, out);
}

// round 12
// speedup vs baseline: 6.5864x; 1.9715x over previous
#include <cuda_runtime.h>
#include <stdint.h>

namespace {
constexpr int N   = 512;
constexpr int D   = 64;
constexpr int C   = 32;
constexpr int HID = 128;
constexpr int NH  = 8;
constexpr int HD  = 16;
constexpr float SCALE_EX2 = 0.25f * 1.4426950408889634f;  // head_dim^-0.5 * log2(e)
constexpr float NEG_BIAS  = -8.0f;                         // fp16 overflow guard (cancels)
constexpr int THREADS = 512;
constexpr int NBT = 96;

// smem byte offsets
constexpr int XSTRIDE = 144;                   // x fp16 row stride (72 halves) — ldm conflict-free
constexpr int OFF_X  = 0;                      // x fp16 [512][72]           = 73728
constexpr int OFF_Q  = 73728;                  // Q fp16 [512][24] (48B)     = 24576
constexpr int OFF_K  = OFF_Q + 24576;          // K fp16 [512][24]
constexpr int OFF_V  = OFF_K + 24576;          // V fp16 [512][24]
constexpr int OFF_W  = OFF_V + 24576;          // W fp16 [48][72] (144B)     = 6912
constexpr int SMEM_BYTES = OFF_W + 6912;       // 154368

// overlays in the dead x region (x is dead after projection)
constexpr int OFF_SX  = 0;                     // sx fp16 [512][24] (48B) = 24576
constexpr int OFF_CLS = 24576;                 // cls fp16 [32][520] (1040B) = 33280
constexpr uint32_t ONES2 = 0x3C003C00u;
}

__device__ __forceinline__ uint32_t s2u(const void* p) {
    uint32_t a;
    asm("{ .reg .u64 t; cvta.to.shared.u64 t, %1; cvt.u32.u64 %0, t; }" : "=r"(a) : "l"(p));
    return a;
}
__device__ __forceinline__ float fast_ex2(float x) {
    float r; asm("ex2.approx.f32 %0, %1;" : "=f"(r) : "f"(x)); return r;
}
__device__ __forceinline__ uint16_t h_of(float v) {
    uint16_t r; asm("cvt.rn.f16.f32 %0, %1;" : "=h"(r) : "f"(v)); return r;
}
__device__ __forceinline__ uint32_t h2_of(float lo, float hi) {
    uint32_t r; asm("cvt.rn.f16x2.f32 %0, %1, %2;" : "=r"(r) : "f"(hi), "f"(lo)); return r;
}
__device__ __forceinline__ uint32_t h2sat(float lo, float hi) {
    uint32_t r;
    asm("cvt.rn.satfinite.f16x2.f32 %0, %1, %2;" : "=r"(r) : "f"(hi), "f"(lo));
    return r;
}
__device__ __forceinline__ void ldm_x4(uint32_t r[4], uint32_t addr) {
    asm volatile("ldmatrix.sync.aligned.m8n8.x4.shared.b16 {%0,%1,%2,%3}, [%4];"
                 : "=r"(r[0]), "=r"(r[1]), "=r"(r[2]), "=r"(r[3]) : "r"(addr));
}
__device__ __forceinline__ void ldm_x4t(uint32_t r[4], uint32_t addr) {
    asm volatile("ldmatrix.sync.aligned.m8n8.x4.trans.shared.b16 {%0,%1,%2,%3}, [%4];"
                 : "=r"(r[0]), "=r"(r[1]), "=r"(r[2]), "=r"(r[3]) : "r"(addr));
}
__device__ __forceinline__ void ldm_x2t(uint32_t& r0, uint32_t& r1, uint32_t addr) {
    asm volatile("ldmatrix.sync.aligned.m8n8.x2.trans.shared.b16 {%0,%1}, [%2];"
                 : "=r"(r0), "=r"(r1) : "r"(addr));
}
__device__ __forceinline__ void mma16816(float* d,
                                         const uint32_t* a, uint32_t b0, uint32_t b1,
                                         float c0, float c1, float c2, float c3) {
    asm volatile("mma.sync.aligned.m16n8k16.row.col.f32.f16.f16.f32 "
                 "{%0,%1,%2,%3}, {%4,%5,%6,%7}, {%8,%9}, {%10,%11,%12,%13};"
                 : "=f"(d[0]), "=f"(d[1]), "=f"(d[2]), "=f"(d[3])
                 : "r"(a[0]), "r"(a[1]), "r"(a[2]), "r"(a[3]), "r"(b0), "r"(b1),
                   "f"(c0), "f"(c1), "f"(c2), "f"(c3));
}

__global__ __launch_bounds__(THREADS, 1)
void spatial_attn_mma2(const float* __restrict__ x, const float* __restrict__ cls,
                       const float* __restrict__ Wq, const float* __restrict__ Wk,
                       const float* __restrict__ Wv, float* __restrict__ out) {
    extern __shared__ char smem[];
    const uint32_t sbase = s2u(smem);

    const int blk = blockIdx.x, h = blk & (NH - 1), bt = blk >> 3;
    const float* xg   = x + (size_t)bt * N * D;
    const float* clsg = cls + (size_t)bt * C * N;
    const int tid = threadIdx.x, lane = tid & 31, wid = tid >> 5;   // 16 warps

    // ---- stage x -> fp16 [512][72] and this head's W -> fp16 [48][72] ----
    for (int i = tid; i < N * D / 4; i += THREADS) {               // 16 iters
        const int row = i >> 4, c4 = i & 15;
        const float4 v4 = *reinterpret_cast<const float4*>(xg + row * D + c4 * 4);
        const uint32_t p0 = h2_of(v4.x, v4.y), p1 = h2_of(v4.z, v4.w);
        *reinterpret_cast<uint2*>(smem + OFF_X + row * XSTRIDE + c4 * 8) =
            make_uint2(p0, p1);
    }
    for (int idx = tid; idx < 3 * HD * D; idx += THREADS) {        // 6 iters
        const int kind = idx >> 10, rem = idx & 1023, e = rem >> 6, d = rem & 63;
        const float* Ws = (kind == 0) ? Wq : (kind == 1) ? Wk : Wv;
        *reinterpret_cast<uint16_t*>(smem + OFF_W + (kind * HD + e) * XSTRIDE + d * 2) =
            h_of(Ws[(h * HD + e) * D + d]);
    }
    __syncthreads();

    // ---- projection via mma: warp owns x rows [wid*32, wid*32+32) ----
    {
        float acc[3][2][2][4];
        #pragma unroll
        for (int k = 0; k < 3; k++)
            #pragma unroll
            for (int mt = 0; mt < 2; mt++)
                #pragma unroll
                for (int nt = 0; nt < 2; nt++)
                    #pragma unroll
                    for (int j = 0; j < 4; j++) acc[k][mt][nt][j] = 0.f;

        const uint32_t arow = (uint32_t)(wid * 32 + (lane & 15));
        const uint32_t ainc = (uint32_t)((lane >> 4) * 16);
        const uint32_t brow = (uint32_t)((lane & 7) + ((lane & 16) ? 8 : 0));
        const uint32_t binc = (uint32_t)((lane & 8) ? 16 : 0);

        #pragma unroll
        for (int j = 0; j < 4; j++) {
            uint32_t ax[2][4];
            ldm_x4(ax[0], sbase + OFF_X + arow * XSTRIDE + ainc + (uint32_t)j * 32u);
            ldm_x4(ax[1], sbase + OFF_X + (arow + 16) * XSTRIDE + ainc + (uint32_t)j * 32u);
            #pragma unroll
            for (int kind = 0; kind < 3; kind++) {
                uint32_t wf[4];
                ldm_x4(wf, sbase + OFF_W + ((uint32_t)kind * 16u + brow) * XSTRIDE + binc
                             + (uint32_t)j * 32u);
                #pragma unroll
                for (int mt = 0; mt < 2; mt++) {
                    mma16816(acc[kind][mt][0], ax[mt], wf[0], wf[1],
                             acc[kind][mt][0][0], acc[kind][mt][0][1],
                             acc[kind][mt][0][2], acc[kind][mt][0][3]);
                    mma16816(acc[kind][mt][1], ax[mt], wf[2], wf[3],
                             acc[kind][mt][1][0], acc[kind][mt][1][1],
                             acc[kind][mt][1][2], acc[kind][mt][1][3]);
                }
            }
        }

        // epilogue: C frags -> fp16 Q/K/V [row][e], stride 48B  (generic pointers!)
        const int g = lane >> 2, cq = (lane & 3) * 2;
        #pragma unroll
        for (int kind = 0; kind < 3; kind++) {
            char* base = smem + (kind == 0 ? OFF_Q : (kind == 1 ? OFF_K : OFF_V));
            #pragma unroll
            for (int mt = 0; mt < 2; mt++) {
                #pragma unroll
                for (int nt = 0; nt < 2; nt++) {
                    float c0 = acc[kind][mt][nt][0], c1 = acc[kind][mt][nt][1];
                    float c2 = acc[kind][mt][nt][2], c3 = acc[kind][mt][nt][3];
                    if (kind == 0) {
                        c0 *= SCALE_EX2; c1 *= SCALE_EX2; c2 *= SCALE_EX2; c3 *= SCALE_EX2;
                    }
                    const int row = wid * 32 + mt * 16 + g;
                    const int eoff = (nt * 8 + cq) * 2;
                    *reinterpret_cast<uint32_t*>(base + row * 48 + eoff)       = h2_of(c0, c1);
                    *reinterpret_cast<uint32_t*>(base + (row + 8) * 48 + eoff) = h2_of(c2, c3);
                }
            }
        }
    }
    __syncthreads();

    // ---- flash attention via mma.sync (R9-proven): warp owns rows [wid*32, +32) ----
    {
        const int rb = wid * 32;
        uint32_t qa[2][4];
        #pragma unroll
        for (int mt = 0; mt < 2; mt++)
            ldm_x4(qa[mt], sbase + OFF_Q + (uint32_t)(rb + mt * 16 + (lane & 15)) * 48u
                                 + (uint32_t)(lane >> 4) * 16u);

        float O[2][2][4], R[2][4];
        #pragma unroll
        for (int mt = 0; mt < 2; mt++) {
            #pragma unroll
            for (int nn = 0; nn < 2; nn++)
                #pragma unroll
                for (int j = 0; j < 4; j++) O[mt][nn][j] = 0.f;
            #pragma unroll
            for (int j = 0; j < 4; j++) R[mt][j] = 0.f;
        }

        const uint32_t koff = (uint32_t)(((lane & 7) + ((lane & 16) ? 8 : 0)) * 48
                                         + ((lane & 8) ? 16 : 0));
        const uint32_t voff = (uint32_t)(((lane & 7) + ((lane & 8) ? 8 : 0)) * 48
                                         + ((lane & 16) ? 16 : 0));

        #pragma unroll 4
        for (int kb = 0; kb < 32; kb++) {
            uint32_t kf[4], vf[4];
            ldm_x4 (kf, sbase + OFF_K + (uint32_t)kb * 768u + koff);
            ldm_x4t(vf, sbase + OFF_V + (uint32_t)kb * 768u + voff);

            #pragma unroll
            for (int mt = 0; mt < 2; mt++) {
                float s0[4], s1[4];
                mma16816(s0, qa[mt], kf[0], kf[1], NEG_BIAS, NEG_BIAS, NEG_BIAS, NEG_BIAS);
                mma16816(s1, qa[mt], kf[2], kf[3], NEG_BIAS, NEG_BIAS, NEG_BIAS, NEG_BIAS);
                uint32_t pa[4];
                pa[0] = h2sat(fast_ex2(s0[0]), fast_ex2(s0[1]));
                pa[1] = h2sat(fast_ex2(s0[2]), fast_ex2(s0[3]));
                pa[2] = h2sat(fast_ex2(s1[0]), fast_ex2(s1[1]));
                pa[3] = h2sat(fast_ex2(s1[2]), fast_ex2(s1[3]));
                mma16816(O[mt][0], pa, vf[0], vf[1],
                         O[mt][0][0], O[mt][0][1], O[mt][0][2], O[mt][0][3]);
                mma16816(O[mt][1], pa, vf[2], vf[3],
                         O[mt][1][0], O[mt][1][1], O[mt][1][2], O[mt][1][3]);
                mma16816(R[mt], pa, ONES2, ONES2,
                         R[mt][0], R[mt][1], R[mt][2], R[mt][3]);
            }
        }

        // normalize + write sx fp16 [512][24] (48B stride) into dead x region
        const int g = lane >> 2, cq = (lane & 3) * 2;
        #pragma unroll
        for (int mt = 0; mt < 2; mt++) {
            const float inv0 = __frcp_rn(R[mt][0]);
            const float inv1 = __frcp_rn(R[mt][2]);
            const int row0 = rb + mt * 16 + g, row1 = row0 + 8;
            #pragma unroll
            for (int nn = 0; nn < 2; nn++) {
                const int eoff = (nn * 8 + cq) * 2;
                *reinterpret_cast<uint32_t*>(smem + OFF_SX + row0 * 48 + eoff) =
                    h2_of(O[mt][nn][0] * inv0, O[mt][nn][1] * inv0);
                *reinterpret_cast<uint32_t*>(smem + OFF_SX + row1 * 48 + eoff) =
                    h2_of(O[mt][nn][2] * inv1, O[mt][nn][3] * inv1);
            }
        }
    }
    __syncthreads();

    // ---- stage cls -> fp16 [32][520] (1040B rows) ----
    for (int i = tid; i < C * N / 4; i += THREADS) {               // 8 iters
        const int c = i >> 7, n4 = i & 127;
        const float4 v4 = *reinterpret_cast<const float4*>(clsg + c * N + n4 * 4);
        const uint32_t p0 = h2_of(v4.x, v4.y), p1 = h2_of(v4.z, v4.w);
        *reinterpret_cast<uint2*>(smem + OFF_CLS + c * 1040 + n4 * 8) = make_uint2(p0, p1);
    }
    __syncthreads();

    // ---- pooling via mma: warps 0..3, warp = (mt, nt); K=512 in 32 steps ----
    if (wid < 4) {
        const int mt = wid & 1, nt = wid >> 1;
        float acc[4] = {0.f, 0.f, 0.f, 0.f};
        const uint32_t aaddr = sbase + OFF_CLS
            + (uint32_t)(mt * 16 + (lane & 15)) * 1040u + (uint32_t)(lane >> 4) * 16u;
        const uint32_t brow = (uint32_t)((lane & 7) + ((lane & 8) ? 8 : 0));

        #pragma unroll 8
        for (int j = 0; j < 32; j++) {
            uint32_t af[4];
            ldm_x4(af, aaddr + (uint32_t)j * 32u);
            uint32_t b0, b1;
            ldm_x2t(b0, b1, sbase + OFF_SX + ((uint32_t)j * 16u + brow) * 48u
                              + (uint32_t)nt * 16u);
            mma16816(acc, af, b0, b1, acc[0], acc[1], acc[2], acc[3]);
        }

        const int g = lane >> 2, cq = (lane & 3) * 2;
        const int c0 = mt * 16 + g;
        const int d  = nt * 8 + cq;
        float2 u;
        u.x = acc[0]; u.y = acc[1];
        *reinterpret_cast<float2*>(out + ((size_t)bt * C + c0) * HID + h * HD + d) = u;
        u.x = acc[2]; u.y = acc[3];
        *reinterpret_cast<float2*>(out + ((size_t)bt * C + c0 + 8) * HID + h * HD + d) = u;
    }
}

extern "C" void kernel_launch(void* const* d_in, const int* in_sizes, int n_in,
                              void* d_out, int out_size) {
    const float* x   = (const float*)d_in[0];
    const float* cls = (const float*)d_in[1];
    const float* Wq  = (const float*)d_in[2];
    const float* Wk  = (const float*)d_in[3];
    const float* Wv  = (const float*)d_in[4];
    float* out = (float*)d_out;

    cudaFuncSetAttribute(spatial_attn_mma2, cudaFuncAttributeMaxDynamicSharedMemorySize,
                         SMEM_BYTES);
    spatial_attn_mma2<<<NBT * NH, THREADS, SMEM_BYTES>>>(x, cls, Wq, Wk, Wv, out);
}